// round 9
// baseline (speedup 1.0000x reference)
#include <cuda_runtime.h>

#define FINF __int_as_float(0x7f800000)

constexpr int BB = 32, HH = 512, WW = 512;
constexpr int TX = 128;           // tile width (outputs)
constexpr int TY = 64;            // tile height (outputs)
constexpr int R  = 7;             // k=15 radius
constexpr int DY = TY + 2 * R;    // 78 halo rows
constexpr int NT = 256;           // 8 warps

__device__ __forceinline__ float cmin3(float a, float b, float c) {
    return fminf(fminf(a, b), c);
}

__global__ __launch_bounds__(NT, 5) void dark_erode(const float* __restrict__ I,
                                                    float* __restrict__ O) {
    __shared__ float hs[DY * TX];  // horizontally-eroded halo tile, pitch 128

    const int tid  = threadIdx.x;
    const int lane = tid & 31;
    const int warp = tid >> 5;
    const int bx = blockIdx.x, by = blockIdx.y, b = blockIdx.z;
    const int W0 = bx * TX;
    const int x0 = W0 + 4 * lane;          // own 4-float block
    const float* base = I + (size_t)b * 3 * HH * WW;
    const bool has_g = (x0 - 8 >= 0);
    const bool has_e = (lane >= 30) && (x0 + 8 < WW);

    // ---- Phase A: coalesced load + channel-min + horizontal 15-min via shuffles ----
    for (int r = warp; r < DY; r += NT / 32) {
        const int gy = by * TY - R + r;
        const bool rowv = (unsigned)gy < (unsigned)HH;
        const float* r0 = base + (size_t)gy * WW;
        const float* r1 = r0 + HH * WW;
        const float* r2 = r1 + HH * WW;

        // block i-2 (x0-8): reduce immediately to suffix stats, free the float4s
        float Sg3 = FINF, Sg2 = FINF, Sg1 = FINF, Fg = FINF;
        if (rowv && has_g) {
            float4 a = *(const float4*)(r0 + x0 - 8);
            float4 c = *(const float4*)(r1 + x0 - 8);
            float4 f = *(const float4*)(r2 + x0 - 8);
            Sg3 = cmin3(a.w, c.w, f.w);
            Sg2 = fminf(cmin3(a.z, c.z, f.z), Sg3);
            Sg1 = fminf(cmin3(a.y, c.y, f.y), Sg2);
            Fg  = fminf(cmin3(a.x, c.x, f.x), Sg1);
        }
        // block i+2 (x0+8), lanes 30/31 only: reduce to prefix stats
        float Pe0 = FINF, Pe1 = FINF, Pe2 = FINF, Fe = FINF;
        if (rowv && has_e) {
            float4 a = *(const float4*)(r0 + x0 + 8);
            float4 c = *(const float4*)(r1 + x0 + 8);
            float4 f = *(const float4*)(r2 + x0 + 8);
            Pe0 = cmin3(a.x, c.x, f.x);
            Pe1 = fminf(Pe0, cmin3(a.y, c.y, f.y));
            Pe2 = fminf(Pe1, cmin3(a.z, c.z, f.z));
            Fe  = fminf(Pe2, cmin3(a.w, c.w, f.w));
        }
        // own block i: prefix stats + full
        float Pd0 = FINF, Pd1 = FINF, Pd2 = FINF, F = FINF;
        if (rowv) {
            float4 a = *(const float4*)(r0 + x0);
            float4 c = *(const float4*)(r1 + x0);
            float4 f = *(const float4*)(r2 + x0);
            Pd0 = cmin3(a.x, c.x, f.x);
            Pd1 = fminf(Pd0, cmin3(a.y, c.y, f.y));
            Pd2 = fminf(Pd1, cmin3(a.z, c.z, f.z));
            F   = fminf(Pd2, cmin3(a.w, c.w, f.w));
        }

        // cross-lane gathers (edges patched by select)
        const unsigned m = 0xffffffffu;
        const float upF  = __shfl_up_sync(m, F, 1);
        const float dnF  = __shfl_down_sync(m, F, 1);
        const float dnFg = __shfl_down_sync(m, Fg, 1);
        const float upFe = __shfl_up_sync(m, Fe, 1);
        const float dnP0 = __shfl_down_sync(m, Pd0, 2);
        const float dnP1 = __shfl_down_sync(m, Pd1, 2);
        const float dnP2 = __shfl_down_sync(m, Pd2, 2);

        const float FL1 = (lane == 0)  ? dnFg : upF;   // full min of block i-1
        const float FR  = (lane == 31) ? upFe : dnF;   // full min of block i+1
        const float Q0  = (lane >= 30) ? Pe0 : dnP0;   // prefix of block i+2
        const float Q1  = (lane >= 30) ? Pe1 : dnP1;
        const float Q2  = (lane >= 30) ? Pe2 : dnP2;

        const float core = fminf(FL1, fminf(F, FR));
        float4 o;
        o.x = fminf(core, Sg1);               // window [x0-7 , x0+7 ]
        o.y = fminf(fminf(core, Sg2), Q0);    // window [x0-6 , x0+8 ]
        o.z = fminf(fminf(core, Sg3), Q1);    // window [x0-5 , x0+9 ]
        o.w = fminf(core, Q2);                // window [x0-4 , x0+10]

        *(float4*)(hs + r * TX + 4 * lane) = o;
    }
    __syncthreads();

    // ---- Phase B: vertical 15-tap min from smem, coalesced output ----
    for (int t = tid; t < TX * (TY / 8); t += NT) {
        const int lx = t & (TX - 1);
        const int yg = t >> 7;                 // TX = 128
        const float* cp = hs + (yg * 8) * TX + lx;

        float w[22];
#pragma unroll
        for (int i = 0; i < 22; i++) w[i] = cp[i * TX];
#pragma unroll
        for (int i = 0; i < 21; i++) w[i] = fminf(w[i], w[i + 1]);
#pragma unroll
        for (int i = 0; i < 19; i++) w[i] = fminf(w[i], w[i + 2]);
#pragma unroll
        for (int i = 0; i < 15; i++) w[i] = fminf(w[i], w[i + 4]);

        float* op = O + ((size_t)b * HH + by * TY + yg * 8) * WW + W0 + lx;
#pragma unroll
        for (int j = 0; j < 8; j++) {
            op[(size_t)j * WW] = fminf(w[j], w[j + 7]);
        }
    }
}

extern "C" void kernel_launch(void* const* d_in, const int* in_sizes, int n_in,
                              void* d_out, int out_size) {
    // Find I by element count (robust to metadata ordering; k=15 baked in).
    const float* I = (const float*)d_in[0];
    for (int i = 0; i < n_in; i++) {
        if (in_sizes[i] == BB * 3 * HH * WW) I = (const float*)d_in[i];
    }
    float* out = (float*)d_out;

    dim3 grid(WW / TX, HH / TY, BB);   // (4, 8, 32) = 1024 blocks
    dark_erode<<<grid, NT>>>(I, out);
}

// round 11
// speedup vs baseline: 1.0814x; 1.0814x over previous
#include <cuda_runtime.h>

#define FINF __int_as_float(0x7f800000)

constexpr int BB = 32, HH = 512, WW = 512;
constexpr int TX = 128;           // tile width (outputs)
constexpr int TY = 32;            // tile height (outputs)
constexpr int R  = 7;             // k=15 radius
constexpr int DY = TY + 2 * R;    // 46 halo rows
constexpr int NT = 128;           // 4 warps

__global__ __launch_bounds__(NT) void dark_erode(const float* __restrict__ I,
                                                 float* __restrict__ O) {
    __shared__ float hs[DY * TX];  // horizontally-eroded halo tile, pitch 128

    const int tid  = threadIdx.x;
    const int lane = tid & 31;
    const int warp = tid >> 5;
    const int bx = blockIdx.x, by = blockIdx.y, b = blockIdx.z;
    const int W0 = bx * TX;
    const int x0 = W0 + 4 * lane;          // own 4-float block
    const float* base = I + (size_t)b * 3 * HH * WW;

    // ---- Phase A: coalesced load + channel-min + horizontal 15-min via shuffles ----
    // Warp w handles halo rows w, w+4, ... Each lane produces 4 outputs/row.
    for (int r = warp; r < DY; r += NT / 32) {
        const int gy = by * TY - R + r;
        const bool rowv = (unsigned)gy < (unsigned)HH;

        float4 d = make_float4(FINF, FINF, FINF, FINF);  // block i   (own)
        float4 g = d;                                    // block i-2 (x0-8)
        float4 e = d;                                    // block i+2 for lanes 30/31 (x0+8)
        if (rowv) {
            const float* r0 = base + (size_t)gy * WW;
            const float* r1 = r0 + HH * WW;
            const float* r2 = r1 + HH * WW;
            {
                float4 a = *(const float4*)(r0 + x0);
                float4 c = *(const float4*)(r1 + x0);
                float4 f = *(const float4*)(r2 + x0);
                d.x = fminf(fminf(a.x, c.x), f.x);
                d.y = fminf(fminf(a.y, c.y), f.y);
                d.z = fminf(fminf(a.z, c.z), f.z);
                d.w = fminf(fminf(a.w, c.w), f.w);
            }
            if (x0 - 8 >= 0) {
                float4 a = *(const float4*)(r0 + x0 - 8);
                float4 c = *(const float4*)(r1 + x0 - 8);
                float4 f = *(const float4*)(r2 + x0 - 8);
                g.x = fminf(fminf(a.x, c.x), f.x);
                g.y = fminf(fminf(a.y, c.y), f.y);
                g.z = fminf(fminf(a.z, c.z), f.z);
                g.w = fminf(fminf(a.w, c.w), f.w);
            }
            if (lane >= 30 && x0 + 8 < WW) {
                float4 a = *(const float4*)(r0 + x0 + 8);
                float4 c = *(const float4*)(r1 + x0 + 8);
                float4 f = *(const float4*)(r2 + x0 + 8);
                e.x = fminf(fminf(a.x, c.x), f.x);
                e.y = fminf(fminf(a.y, c.y), f.y);
                e.z = fminf(fminf(a.z, c.z), f.z);
                e.w = fminf(fminf(a.w, c.w), f.w);
            }
        }

        // per-block stats
        const float Pd0 = d.x;
        const float Pd1 = fminf(d.x, d.y);
        const float Pd2 = fminf(Pd1, d.z);
        const float F   = fminf(Pd2, d.w);
        const float Sg3 = g.w;
        const float Sg2 = fminf(g.z, g.w);
        const float Sg1 = fminf(g.y, Sg2);
        const float Fg  = fminf(g.x, Sg1);
        const float Pe0 = e.x;
        const float Pe1 = fminf(e.x, e.y);
        const float Pe2 = fminf(Pe1, e.z);
        const float Fe  = fminf(Pe2, e.w);

        // cross-lane gathers (all lanes participate; edges patched by select)
        const unsigned m = 0xffffffffu;
        const float upF  = __shfl_up_sync(m, F, 1);
        const float dnF  = __shfl_down_sync(m, F, 1);
        const float dnFg = __shfl_down_sync(m, Fg, 1);
        const float upFe = __shfl_up_sync(m, Fe, 1);
        const float dnP0 = __shfl_down_sync(m, Pd0, 2);
        const float dnP1 = __shfl_down_sync(m, Pd1, 2);
        const float dnP2 = __shfl_down_sync(m, Pd2, 2);

        const float FL1 = (lane == 0)  ? dnFg : upF;   // full min of block i-1
        const float FR  = (lane == 31) ? upFe : dnF;   // full min of block i+1
        const float Q0  = (lane >= 30) ? Pe0 : dnP0;   // prefix of block i+2
        const float Q1  = (lane >= 30) ? Pe1 : dnP1;
        const float Q2  = (lane >= 30) ? Pe2 : dnP2;

        const float core = fminf(FL1, fminf(F, FR));
        float4 o;
        o.x = fminf(core, Sg1);               // window [x0-7 , x0+7 ]
        o.y = fminf(fminf(core, Sg2), Q0);    // window [x0-6 , x0+8 ]
        o.z = fminf(fminf(core, Sg3), Q1);    // window [x0-5 , x0+9 ]
        o.w = fminf(core, Q2);                // window [x0-4 , x0+10]

        *(float4*)(hs + r * TX + 4 * lane) = o;
    }
    __syncthreads();

    // ---- Phase B: vertical 15-tap min from smem, coalesced output ----
    // task = (column lx) x (y-group of 8). Lane stride 1 float -> conflict-free LDS.
    for (int t = tid; t < TX * (TY / 8); t += NT) {
        const int lx = t & (TX - 1);
        const int yg = t >> 7;                 // TX = 128
        const float* cp = hs + (yg * 8) * TX + lx;

        float w[22];
#pragma unroll
        for (int i = 0; i < 22; i++) w[i] = cp[i * TX];
        // in-place window doubling: m2, m4, m8
#pragma unroll
        for (int i = 0; i < 21; i++) w[i] = fminf(w[i], w[i + 1]);
#pragma unroll
        for (int i = 0; i < 19; i++) w[i] = fminf(w[i], w[i + 2]);
#pragma unroll
        for (int i = 0; i < 15; i++) w[i] = fminf(w[i], w[i + 4]);

        float* op = O + ((size_t)b * HH + by * TY + yg * 8) * WW + W0 + lx;
#pragma unroll
        for (int j = 0; j < 8; j++) {
            op[(size_t)j * WW] = fminf(w[j], w[j + 7]);
        }
    }
}

extern "C" void kernel_launch(void* const* d_in, const int* in_sizes, int n_in,
                              void* d_out, int out_size) {
    // Find I by element count (robust to metadata ordering; k=15 baked in).
    const float* I = (const float*)d_in[0];
    for (int i = 0; i < n_in; i++) {
        if (in_sizes[i] == BB * 3 * HH * WW) I = (const float*)d_in[i];
    }
    float* out = (float*)d_out;

    dim3 grid(WW / TX, HH / TY, BB);   // (4, 16, 32) = 2048 blocks
    dark_erode<<<grid, NT>>>(I, out);
}

// round 12
// speedup vs baseline: 1.4305x; 1.3228x over previous
#include <cuda_runtime.h>

#define FINF __int_as_float(0x7f800000)

constexpr int BB = 32, HH = 512, WW = 512;
constexpr int TX = 128;           // tile width (outputs)
constexpr int TY = 64;            // tile height (outputs)
constexpr int R  = 7;             // k=15 radius
constexpr int DY = TY + 2 * R;    // 78 halo rows
constexpr int NT = 256;           // 8 warps

__device__ __forceinline__ float cmin3(float a, float b, float c) {
    return fminf(fminf(a, b), c);
}

__global__ __launch_bounds__(NT) void dark_erode(const float* __restrict__ I,
                                                 float* __restrict__ O) {
    __shared__ float hs[DY * TX];  // horizontally-eroded halo tile, pitch 128

    const int tid  = threadIdx.x;
    const int lane = tid & 31;
    const int warp = tid >> 5;
    const int bx = blockIdx.x, by = blockIdx.y, b = blockIdx.z;
    const int W0 = bx * TX;
    const int x0 = W0 + 4 * lane;          // own 4-float block
    const float* base = I + (size_t)b * 3 * HH * WW;
    const bool is_gl = (lane < 2)   && (x0 - 8 >= 0);   // left-edge halo loader
    const bool is_el = (lane >= 30) && (x0 + 8 < WW);   // right-edge halo loader

    // ---- Phase A: coalesced load + channel-min + horizontal 15-min via shuffles ----
    // Each lane loads ONLY its own 4-px block per channel; neighbor-block stats
    // come from warp shuffles. Lanes 0-1 / 30-31 additionally load the tile-edge
    // halo blocks (x0-8 / x0+8).
    for (int r = warp; r < DY; r += NT / 32) {
        const int gy = by * TY - R + r;
        const bool rowv = (unsigned)gy < (unsigned)HH;

        float4 d  = make_float4(FINF, FINF, FINF, FINF);  // own block i
        float4 gv = d;                                    // block i-2 (edge lanes only)
        float4 ev = d;                                    // block i+2 (edge lanes only)
        if (rowv) {
            const float* r0 = base + (size_t)gy * WW;
            const float* r1 = r0 + HH * WW;
            const float* r2 = r1 + HH * WW;
            {
                float4 a = *(const float4*)(r0 + x0);
                float4 c = *(const float4*)(r1 + x0);
                float4 f = *(const float4*)(r2 + x0);
                d.x = cmin3(a.x, c.x, f.x);
                d.y = cmin3(a.y, c.y, f.y);
                d.z = cmin3(a.z, c.z, f.z);
                d.w = cmin3(a.w, c.w, f.w);
            }
            if (is_gl) {
                float4 a = *(const float4*)(r0 + x0 - 8);
                float4 c = *(const float4*)(r1 + x0 - 8);
                float4 f = *(const float4*)(r2 + x0 - 8);
                gv.x = cmin3(a.x, c.x, f.x);
                gv.y = cmin3(a.y, c.y, f.y);
                gv.z = cmin3(a.z, c.z, f.z);
                gv.w = cmin3(a.w, c.w, f.w);
            }
            if (is_el) {
                float4 a = *(const float4*)(r0 + x0 + 8);
                float4 c = *(const float4*)(r1 + x0 + 8);
                float4 f = *(const float4*)(r2 + x0 + 8);
                ev.x = cmin3(a.x, c.x, f.x);
                ev.y = cmin3(a.y, c.y, f.y);
                ev.z = cmin3(a.z, c.z, f.z);
                ev.w = cmin3(a.w, c.w, f.w);
            }
        }

        // own-block stats: prefixes (P), suffixes (S), full (F)
        const float P0 = d.x;
        const float P1 = fminf(P0, d.y);
        const float P2 = fminf(P1, d.z);
        const float F  = fminf(P2, d.w);
        const float S3 = d.w;
        const float S2 = fminf(d.z, S3);
        const float S1 = fminf(d.y, S2);
        // edge-block stats
        const float gS3 = gv.w;
        const float gS2 = fminf(gv.z, gS3);
        const float gS1 = fminf(gv.y, gS2);
        const float gF  = fminf(gv.x, gS1);
        const float eP0 = ev.x;
        const float eP1 = fminf(eP0, ev.y);
        const float eP2 = fminf(eP1, ev.z);
        const float eF  = fminf(eP2, ev.w);

        // cross-lane gathers
        const unsigned m = 0xffffffffu;
        const float upF   = __shfl_up_sync(m, F, 1);     // full(i-1)
        const float dnF   = __shfl_down_sync(m, F, 1);   // full(i+1)
        const float dn_gF = __shfl_down_sync(m, gF, 1);  // lane1's gF -> lane0
        const float up_eF = __shfl_up_sync(m, eF, 1);    // lane30's eF -> lane31
        const float upS1  = __shfl_up_sync(m, S1, 2);    // suffix(i-2)
        const float upS2  = __shfl_up_sync(m, S2, 2);
        const float upS3  = __shfl_up_sync(m, S3, 2);
        const float dnP0  = __shfl_down_sync(m, P0, 2);  // prefix(i+2)
        const float dnP1  = __shfl_down_sync(m, P1, 2);
        const float dnP2  = __shfl_down_sync(m, P2, 2);

        const float FL1 = (lane == 0)  ? dn_gF : upF;   // full min of block i-1
        const float FR  = (lane == 31) ? up_eF : dnF;   // full min of block i+1
        const float Sg1 = (lane < 2)  ? gS1 : upS1;     // suffixes of block i-2
        const float Sg2 = (lane < 2)  ? gS2 : upS2;
        const float Sg3 = (lane < 2)  ? gS3 : upS3;
        const float Q0  = (lane >= 30) ? eP0 : dnP0;    // prefixes of block i+2
        const float Q1  = (lane >= 30) ? eP1 : dnP1;
        const float Q2  = (lane >= 30) ? eP2 : dnP2;

        const float core = cmin3(FL1, F, FR);
        float4 o;
        o.x = fminf(core, Sg1);               // window [x0-7 , x0+7 ]
        o.y = fminf(fminf(core, Sg2), Q0);    // window [x0-6 , x0+8 ]
        o.z = fminf(fminf(core, Sg3), Q1);    // window [x0-5 , x0+9 ]
        o.w = fminf(core, Q2);                // window [x0-4 , x0+10]

        *(float4*)(hs + r * TX + 4 * lane) = o;
    }
    __syncthreads();

    // ---- Phase B: vertical 15-tap min from smem, coalesced output ----
    for (int t = tid; t < TX * (TY / 8); t += NT) {
        const int lx = t & (TX - 1);
        const int yg = t >> 7;                 // TX = 128
        const float* cp = hs + (yg * 8) * TX + lx;

        float w[22];
#pragma unroll
        for (int i = 0; i < 22; i++) w[i] = cp[i * TX];
#pragma unroll
        for (int i = 0; i < 21; i++) w[i] = fminf(w[i], w[i + 1]);
#pragma unroll
        for (int i = 0; i < 19; i++) w[i] = fminf(w[i], w[i + 2]);
#pragma unroll
        for (int i = 0; i < 15; i++) w[i] = fminf(w[i], w[i + 4]);

        float* op = O + ((size_t)b * HH + by * TY + yg * 8) * WW + W0 + lx;
#pragma unroll
        for (int j = 0; j < 8; j++) {
            op[(size_t)j * WW] = fminf(w[j], w[j + 7]);
        }
    }
}

extern "C" void kernel_launch(void* const* d_in, const int* in_sizes, int n_in,
                              void* d_out, int out_size) {
    // Find I by element count (robust to metadata ordering; k=15 baked in).
    const float* I = (const float*)d_in[0];
    for (int i = 0; i < n_in; i++) {
        if (in_sizes[i] == BB * 3 * HH * WW) I = (const float*)d_in[i];
    }
    float* out = (float*)d_out;

    dim3 grid(WW / TX, HH / TY, BB);   // (4, 8, 32) = 1024 blocks
    dark_erode<<<grid, NT>>>(I, out);
}